// round 4
// baseline (speedup 1.0000x reference)
#include <cuda_runtime.h>

#define NN 10000
#define NE 320000
#define HD 64
#define NLAYERS 4
#define TE 256   // edges per tile (edge kernel)
#define TNN 64   // nodes per tile (node kernel)

typedef unsigned long long ull;

// ---------------- scratch state (allocation-free) ----------------
__device__ __align__(16) float g_h[NN * HD];
__device__ __align__(16) float g_agg[NN * HD];
__device__ float g_x[NN * 3];
__device__ float g_v[NN * 3];
__device__ float g_iv[NN * 3];
__device__ float g_acc3[NN * 3];
__device__ float g_cnt[NN];
__device__ int g_edge64;

__device__ __forceinline__ float silu_f(float x) {
    return __fdividef(x, 1.0f + __expf(-x));
}

// packed f32x2 helpers
__device__ __forceinline__ ull d2(float x) {
    ull r;
    unsigned u = __float_as_uint(x);
    asm("mov.b64 %0, {%1, %1};" : "=l"(r) : "r"(u));
    return r;
}
__device__ __forceinline__ ull ffma2(ull a, ull b, ull c) {
    ull d;
    asm("fma.rn.f32x2 %0, %1, %2, %3;" : "=l"(d) : "l"(a), "l"(b), "l"(c));
    return d;
}
__device__ __forceinline__ float2 u2f(ull v) {
    unsigned lo, hi;
    asm("mov.b64 {%0, %1}, %2;" : "=r"(lo), "=r"(hi) : "l"(v));
    return make_float2(__uint_as_float(lo), __uint_as_float(hi));
}

__device__ __forceinline__ int sidx(int k, int e, int RW) {
    return k * RW + ((((e >> 2) ^ ((k >> 2) & 7)) << 2) | (e & 3));
}

__device__ __forceinline__ int edge_idx(const void* edges, long long i) {
    if (g_edge64) return (int)((const long long*)edges)[i];
    return ((const int*)edges)[i];
}

__global__ void k_detect(const void* edges) {
    const int* p = (const int*)edges;
    int is64 = 1;
    for (int i = 1; i < 64; i += 2)
        if (p[i] != 0) is64 = 0;
    g_edge64 = is64;
}

__global__ void k_init(const float* __restrict__ his, const float* __restrict__ loc,
                       const float* __restrict__ vel, const float* __restrict__ emb_w,
                       const float* __restrict__ emb_b) {
    int idx = blockIdx.x * blockDim.x + threadIdx.x;
    if (idx < NN * HD) {
        int n = idx >> 6, j = idx & 63;
        float a = emb_b[j];
#pragma unroll
        for (int i = 0; i < 4; i++) a = fmaf(his[n * 4 + i], emb_w[i * 64 + j], a);
        g_h[idx] = a;
        g_agg[idx] = 0.f;
    }
    if (idx < NN * 3) {
        g_x[idx] = loc[idx];
        g_v[idx] = vel[idx];
        g_acc3[idx] = 0.f;
    }
    if (idx < NN) {
        float vx = vel[idx * 3], vy = vel[idx * 3 + 1], vz = vel[idx * 3 + 2];
        float inv = 1.0f / (sqrtf(vx * vx + vy * vy + vz * vz) + 1e-8f);
        g_iv[idx * 3] = vx * inv;
        g_iv[idx * 3 + 1] = vy * inv;
        g_iv[idx * 3 + 2] = vz * inv;
        g_cnt[idx] = 0.f;
    }
}

// ---- broadcast-weight FFMA2 GEMM: warp owns 8 features, lane owns 4 edges ----
// st: staging pre-offset to this warp's 128-edge half; RW = full row width.
// acc[f][p]: feature f (0..7 within octet), edge-pair p (0..1).
template <int RW>
__device__ __forceinline__ void gemm8x4(const float* __restrict__ st,
                                        const float* __restrict__ w,
                                        const float* __restrict__ bias,
                                        ull (&acc)[8][2], int wf, int lane, int K) {
#pragma unroll
    for (int f = 0; f < 8; f++) {
        ull bb = d2(bias[8 * wf + f]);
        acc[f][0] = bb;
        acc[f][1] = bb;
    }
    const float* ap = st + 4 * lane;
    const float* wp = w + 8 * wf;
#pragma unroll 2
    for (int k = 0; k < K; k++) {
        ulonglong2 a = *(const ulonglong2*)(ap + k * RW);
        float4 w0 = *(const float4*)(wp + k * 64);       // broadcast across warp
        float4 w1 = *(const float4*)(wp + k * 64 + 4);   // broadcast
        ull b0 = d2(w0.x), b1 = d2(w0.y), b2 = d2(w0.z), b3 = d2(w0.w);
        ull b4 = d2(w1.x), b5 = d2(w1.y), b6 = d2(w1.z), b7 = d2(w1.w);
        acc[0][0] = ffma2(a.x, b0, acc[0][0]);
        acc[0][1] = ffma2(a.y, b0, acc[0][1]);
        acc[1][0] = ffma2(a.x, b1, acc[1][0]);
        acc[1][1] = ffma2(a.y, b1, acc[1][1]);
        acc[2][0] = ffma2(a.x, b2, acc[2][0]);
        acc[2][1] = ffma2(a.y, b2, acc[2][1]);
        acc[3][0] = ffma2(a.x, b3, acc[3][0]);
        acc[3][1] = ffma2(a.y, b3, acc[3][1]);
        acc[4][0] = ffma2(a.x, b4, acc[4][0]);
        acc[4][1] = ffma2(a.y, b4, acc[4][1]);
        acc[5][0] = ffma2(a.x, b5, acc[5][0]);
        acc[5][1] = ffma2(a.y, b5, acc[5][1]);
        acc[6][0] = ffma2(a.x, b6, acc[6][0]);
        acc[6][1] = ffma2(a.y, b6, acc[6][1]);
        acc[7][0] = ffma2(a.x, b7, acc[7][0]);
        acc[7][1] = ffma2(a.y, b7, acc[7][1]);
    }
}

// silu + feature-major store of the warp's 8x4 tile (st pre-offset to edge half)
template <int RW>
__device__ __forceinline__ void store8x4(float* st, ull (&acc)[8][2], int wf, int lane) {
#pragma unroll
    for (int f = 0; f < 8; f++) {
        float2 lo = u2f(acc[f][0]), hi = u2f(acc[f][1]);
        float4 v = make_float4(silu_f(lo.x), silu_f(lo.y), silu_f(hi.x), silu_f(hi.y));
        *(float4*)(st + (8 * wf + f) * RW + 4 * lane) = v;
    }
}

// ---------------- edge kernel: 256-edge tiles, 512 threads ----------------
__global__ void __launch_bounds__(512, 1)
    k_edge(const void* __restrict__ edges, const float* __restrict__ edge_attr,
           const float* __restrict__ ew1, const float* __restrict__ eb1,
           const float* __restrict__ ew2, const float* __restrict__ eb2,
           const float* __restrict__ cw1, const float* __restrict__ cb1,
           const float* __restrict__ cw2) {
    extern __shared__ float sm[];
    float* w1s = sm;                    // 8384
    float* w2s = w1s + 8384;            // 4096
    float* w3s = w2s + 4096;            // 4096
    float* ins = w3s + 4096;            // 131*256 = 33536
    float* part = ins + 33536;          // 8*256 gate partials
    float* b1s = part + 2048;           // 64
    float* b2s = b1s + 64;
    float* b3s = b2s + 64;
    float* c2s = b3s + 64;
    float* cds = c2s + 64;              // 3*256
    int* rs = (int*)(cds + 768);        // 256
    int* cs = rs + 256;                 // 256

    const int tid = threadIdx.x;
    const int lane = tid & 31;
    const int warp = tid >> 5;
    const int wf = warp & 7;    // feature octet
    const int we = warp >> 3;   // edge half (0/1)
    const int e = tid & 255;
    const int s = tid >> 8;

    for (int i = tid; i < 2096; i += 512) ((float4*)w1s)[i] = ((const float4*)ew1)[i];
    for (int i = tid; i < 1024; i += 512) {
        ((float4*)w2s)[i] = ((const float4*)ew2)[i];
        ((float4*)w3s)[i] = ((const float4*)cw1)[i];
    }
    if (tid < 64) {
        b1s[tid] = eb1[tid];
        b2s[tid] = eb2[tid];
        b3s[tid] = cb1[tid];
        c2s[tid] = cw2[tid];
    }

    const int ntile = NE / TE;
    for (int t = blockIdx.x; t < ntile; t += gridDim.x) {
        __syncthreads();
        long long e0 = (long long)t * TE;
        if (tid < TE) {
            rs[tid] = edge_idx(edges, e0 + tid);
            cs[tid] = edge_idx(edges, (long long)NE + e0 + tid);
        }
        __syncthreads();
        if (tid < TE) {
            int r = rs[e], c = cs[e];
            float dx = g_x[r * 3] - g_x[c * 3];
            float dy = g_x[r * 3 + 1] - g_x[c * 3 + 1];
            float dz = g_x[r * 3 + 2] - g_x[c * 3 + 2];
            cds[e] = dx;
            cds[256 + e] = dy;
            cds[512 + e] = dz;
            ins[128 * 256 + e] = dx * dx + dy * dy + dz * dz;
            float2 ea = *(const float2*)&edge_attr[(e0 + e) * 2];
            ins[129 * 256 + e] = ea.x;
            ins[130 * 256 + e] = ea.y;
        }
        // gather: s=0 -> h[row] (rows 0..63), s=1 -> h[col] (rows 64..127)
        {
            int node = (s == 0) ? rs[e] : cs[e];
            const float4* hp = (const float4*)&g_h[node * 64];
#pragma unroll
            for (int q = 0; q < 16; q++) {
                float4 hv = hp[q];
                int r0 = s * 64 + 4 * q;
                ins[(r0 + 0) * 256 + e] = hv.x;
                ins[(r0 + 1) * 256 + e] = hv.y;
                ins[(r0 + 2) * 256 + e] = hv.z;
                ins[(r0 + 3) * 256 + e] = hv.w;
            }
        }
        __syncthreads();

        float* stw = ins + we * 128;   // this warp's edge half
        ull acc[8][2];
        // GEMM1: [256e,131]@[131,64] + b1, silu
        gemm8x4<256>(stw, w1s, b1s, acc, wf, lane, 131);
        __syncthreads();
        store8x4<256>(stw, acc, wf, lane);
        __syncthreads();

        // GEMM2: @[64,64] + b2, silu -> ef
        gemm8x4<256>(stw, w2s, b2s, acc, wf, lane, 64);
        __syncthreads();
        store8x4<256>(stw, acc, wf, lane);
        __syncthreads();

        // GEMM3: ef@cw1 + b3, silu, dot cw2 -> per-warp gate partials
        gemm8x4<256>(stw, w3s, b3s, acc, wf, lane, 64);
        {
            float g0 = 0.f, g1 = 0.f, g2 = 0.f, g3 = 0.f;
#pragma unroll
            for (int f = 0; f < 8; f++) {
                float c = c2s[8 * wf + f];
                float2 lo = u2f(acc[f][0]), hi = u2f(acc[f][1]);
                g0 = fmaf(silu_f(lo.x), c, g0);
                g1 = fmaf(silu_f(lo.y), c, g1);
                g2 = fmaf(silu_f(hi.x), c, g2);
                g3 = fmaf(silu_f(hi.y), c, g3);
            }
            *(float4*)(part + wf * 256 + we * 128 + 4 * lane) = make_float4(g0, g1, g2, g3);
        }
        __syncthreads();

        // scatter: agg += ef, acc3 += cd*gate, cnt += 1
        {
            int r = rs[e];
#pragma unroll
            for (int q = 0; q < 32; q++) {
                int f = s * 32 + q;
                atomicAdd(&g_agg[r * 64 + f], ins[f * 256 + e]);
            }
            if (s == 0) {
                float gg = 0.f;
#pragma unroll
                for (int w8 = 0; w8 < 8; w8++) gg += part[w8 * 256 + e];
                atomicAdd(&g_acc3[r * 3 + 0], cds[e] * gg);
                atomicAdd(&g_acc3[r * 3 + 1], cds[256 + e] * gg);
                atomicAdd(&g_acc3[r * 3 + 2], cds[512 + e] * gg);
                atomicAdd(&g_cnt[r], 1.0f);
            }
        }
    }
}

// ======== node kernel (unchanged from R2) ========
template <int RW>
__device__ __forceinline__ void gemm_t(const float* __restrict__ st,
                                       const float* __restrict__ w,
                                       const float* __restrict__ bias,
                                       ull (&acc)[4][4], int fc, int er, int K) {
#pragma unroll
    for (int j = 0; j < 4; j++) {
        ull bb = d2(bias[4 * fc + j]);
#pragma unroll
        for (int p = 0; p < 4; p++) acc[p][j] = bb;
    }
    const int eg0 = 2 * er, eg1 = 2 * er + 1;
#pragma unroll 2
    for (int k0 = 0; k0 < K; k0 += 4) {
        int ss = (k0 >> 2) & 7;
        int o0 = ((eg0 ^ ss) << 2), o1 = ((eg1 ^ ss) << 2);
#pragma unroll
        for (int kk = 0; kk < 4; kk++) {
            const float* rp = st + (k0 + kk) * RW;
            ulonglong2 aA = *(const ulonglong2*)(rp + o0);
            ulonglong2 aB = *(const ulonglong2*)(rp + o1);
            float4 wv = *(const float4*)(w + (k0 + kk) * 64 + 4 * fc);
            ull b0 = d2(wv.x), b1 = d2(wv.y), b2 = d2(wv.z), b3 = d2(wv.w);
            acc[0][0] = ffma2(aA.x, b0, acc[0][0]);
            acc[1][0] = ffma2(aA.y, b0, acc[1][0]);
            acc[2][0] = ffma2(aB.x, b0, acc[2][0]);
            acc[3][0] = ffma2(aB.y, b0, acc[3][0]);
            acc[0][1] = ffma2(aA.x, b1, acc[0][1]);
            acc[1][1] = ffma2(aA.y, b1, acc[1][1]);
            acc[2][1] = ffma2(aB.x, b1, acc[2][1]);
            acc[3][1] = ffma2(aB.y, b1, acc[3][1]);
            acc[0][2] = ffma2(aA.x, b2, acc[0][2]);
            acc[1][2] = ffma2(aA.y, b2, acc[1][2]);
            acc[2][2] = ffma2(aB.x, b2, acc[2][2]);
            acc[3][2] = ffma2(aB.y, b2, acc[3][2]);
            acc[0][3] = ffma2(aA.x, b3, acc[0][3]);
            acc[1][3] = ffma2(aA.y, b3, acc[1][3]);
            acc[2][3] = ffma2(aB.x, b3, acc[2][3]);
            acc[3][3] = ffma2(aB.y, b3, acc[3][3]);
        }
    }
}

template <int RW>
__device__ __forceinline__ void store_silu_t(float* st, ull (&acc)[4][4], int fc, int er) {
    int ss = fc & 7;
    int o0 = (((2 * er) ^ ss) << 2), o1 = (((2 * er + 1) ^ ss) << 2);
#pragma unroll
    for (int j = 0; j < 4; j++) {
        int r = 4 * fc + j;
        float2 f0 = u2f(acc[0][j]), f1 = u2f(acc[1][j]);
        float2 f2 = u2f(acc[2][j]), f3 = u2f(acc[3][j]);
        float4 v0 = make_float4(silu_f(f0.x), silu_f(f0.y), silu_f(f1.x), silu_f(f1.y));
        float4 v1 = make_float4(silu_f(f2.x), silu_f(f2.y), silu_f(f3.x), silu_f(f3.y));
        *(float4*)(st + r * RW + o0) = v0;
        *(float4*)(st + r * RW + o1) = v1;
    }
}

__global__ void __launch_bounds__(128, 2)
    k_node(const float* __restrict__ nw1, const float* __restrict__ nb1,
           const float* __restrict__ nw2, const float* __restrict__ nb2,
           const float* __restrict__ vw1, const float* __restrict__ vb1,
           const float* __restrict__ vw2, const float* __restrict__ vb2) {
    extern __shared__ float sm[];
    float* wn1 = sm;
    float* wn2 = wn1 + 8192;
    float* wv1 = wn2 + 4096;
    float* us = wv1 + 4096;
    float* nb1s = us + 8192;
    float* nb2s = nb1s + 64;
    float* vb1s = nb2s + 64;
    float* vw2s = vb1s + 64;
    float* phis = vw2s + 64;

    const int tid = threadIdx.x;
    const int fc = tid & 15;
    const int er = tid >> 4;

    for (int i = tid; i < 2048; i += 128) ((float4*)wn1)[i] = ((const float4*)nw1)[i];
    for (int i = tid; i < 1024; i += 128) {
        ((float4*)wn2)[i] = ((const float4*)nw2)[i];
        ((float4*)wv1)[i] = ((const float4*)vw1)[i];
    }
    if (tid < 64) {
        nb1s[tid] = nb1[tid];
        nb2s[tid] = nb2[tid];
        vb1s[tid] = vb1[tid];
        vw2s[tid] = vw2[tid];
    }
    const float vb2v = vb2[0];

    const int e = tid & 63;
    const int half = tid >> 6;
    const int ntile = (NN + TNN - 1) / TNN;
    for (int t = blockIdx.x; t < ntile; t += gridDim.x) {
        __syncthreads();
        int n0 = t * TNN;
        int n = n0 + e;
#pragma unroll
        for (int q = 0; q < 8; q++) {
            int kq = half * 8 + q;
            float4 hv = make_float4(0, 0, 0, 0), av = make_float4(0, 0, 0, 0);
            if (n < NN) {
                hv = *(const float4*)&g_h[n * 64 + 4 * kq];
                av = *(const float4*)&g_agg[n * 64 + 4 * kq];
            }
            us[sidx(4 * kq + 0, e, 64)] = hv.x;
            us[sidx(4 * kq + 1, e, 64)] = hv.y;
            us[sidx(4 * kq + 2, e, 64)] = hv.z;
            us[sidx(4 * kq + 3, e, 64)] = hv.w;
            us[sidx(64 + 4 * kq + 0, e, 64)] = av.x;
            us[sidx(64 + 4 * kq + 1, e, 64)] = av.y;
            us[sidx(64 + 4 * kq + 2, e, 64)] = av.z;
            us[sidx(64 + 4 * kq + 3, e, 64)] = av.w;
        }
        __syncthreads();

        ull acc[4][4];
        gemm_t<64>(us, wv1, vb1s, acc, fc, er, 64);
        {
            float g[8] = {0.f, 0.f, 0.f, 0.f, 0.f, 0.f, 0.f, 0.f};
#pragma unroll
            for (int p = 0; p < 4; p++)
#pragma unroll
                for (int j = 0; j < 4; j++) {
                    float2 f = u2f(acc[p][j]);
                    float c = vw2s[4 * fc + j];
                    g[2 * p] = fmaf(silu_f(f.x), c, g[2 * p]);
                    g[2 * p + 1] = fmaf(silu_f(f.y), c, g[2 * p + 1]);
                }
#pragma unroll
            for (int m = 1; m < 16; m <<= 1)
#pragma unroll
                for (int i = 0; i < 8; i++)
                    g[i] += __shfl_xor_sync(0xffffffffu, g[i], m);
            if (fc == 0)
#pragma unroll
                for (int i = 0; i < 8; i++) phis[8 * er + i] = g[i] + vb2v;
        }

        gemm_t<64>(us, wn1, nb1s, acc, fc, er, 128);
        __syncthreads();
        store_silu_t<64>(us + 64 * 64, acc, fc, er);
        __syncthreads();

        gemm_t<64>(us + 64 * 64, wn2, nb2s, acc, fc, er, 64);
#pragma unroll
        for (int p = 0; p < 4; p++) {
            int nlo = n0 + 8 * er + 2 * p, nhi = nlo + 1;
#pragma unroll
            for (int j = 0; j < 4; j++) {
                float2 f = u2f(acc[p][j]);
                if (nlo < NN) g_h[nlo * 64 + 4 * fc + j] += f.x;
                if (nhi < NN) g_h[nhi * 64 + 4 * fc + j] += f.y;
            }
        }

        if (tid < TNN) {
            int nu = n0 + tid;
            if (nu < NN) {
                float cnt = g_cnt[nu];
                float inv = 1.0f / fmaxf(cnt, 1.0f);
                float phi = phis[tid];
#pragma unroll
                for (int d = 0; d < 3; d++) {
                    float a = g_acc3[nu * 3 + d] * inv;
                    float vn = g_v[nu * 3 + d] + a + phi * g_iv[nu * 3 + d];
                    g_v[nu * 3 + d] = vn;
                    g_x[nu * 3 + d] += vn;
                    g_acc3[nu * 3 + d] = 0.f;
                }
                g_cnt[nu] = 0.f;
            }
        }
        for (int i = tid; i < TNN * 64; i += 128) {
            int nz = n0 + (i >> 6);
            if (nz < NN) g_agg[nz * 64 + (i & 63)] = 0.f;
        }
    }
}

// ---------------- output: [x | h | v] ----------------
__global__ void k_copyout(float* __restrict__ out) {
    int i = blockIdx.x * blockDim.x + threadIdx.x;
    if (i < NN * 3) out[i] = g_x[i];
    if (i < NN * HD) out[NN * 3 + i] = g_h[i];
    if (i < NN * 3) out[NN * 3 + NN * HD + i] = g_v[i];
}

extern "C" void kernel_launch(void* const* d_in, const int* in_sizes, int n_in,
                              void* d_out, int out_size) {
    const float* his = (const float*)d_in[0];
    const float* loc = (const float*)d_in[1];
    const void* edges = d_in[2];
    const float* vel = (const float*)d_in[3];
    const float* eattr = (const float*)d_in[4];
    const float* emb_w = (const float*)d_in[5];
    const float* emb_b = (const float*)d_in[6];
    const float* ew1 = (const float*)d_in[7];
    const float* eb1 = (const float*)d_in[8];
    const float* ew2 = (const float*)d_in[9];
    const float* eb2 = (const float*)d_in[10];
    const float* nw1 = (const float*)d_in[11];
    const float* nb1 = (const float*)d_in[12];
    const float* nw2 = (const float*)d_in[13];
    const float* nb2 = (const float*)d_in[14];
    const float* cw1 = (const float*)d_in[15];
    const float* cb1 = (const float*)d_in[16];
    const float* cw2 = (const float*)d_in[17];
    const float* vw1 = (const float*)d_in[18];
    const float* vb1 = (const float*)d_in[19];
    const float* vw2 = (const float*)d_in[20];
    const float* vb2 = (const float*)d_in[21];

    // edge smem: w(16576) + ins(33536) + part(2048) + biases(256) + cds(768) = 53184 floats
    size_t esm = (size_t)53184 * 4 + 512 * sizeof(int);
    size_t nsm = (size_t)(8192 + 4096 + 4096 + 8192 + 4 * 64 + 64) * 4;
    cudaFuncSetAttribute(k_edge, cudaFuncAttributeMaxDynamicSharedMemorySize, (int)esm);
    cudaFuncSetAttribute(k_node, cudaFuncAttributeMaxDynamicSharedMemorySize, (int)nsm);

    k_detect<<<1, 1>>>(edges);
    k_init<<<(NN * HD + 255) / 256, 256>>>(his, loc, vel, emb_w, emb_b);
    for (int l = 0; l < NLAYERS; l++) {
        k_edge<<<148, 512, esm>>>(edges, eattr, ew1, eb1, ew2, eb2, cw1, cb1, cw2);
        k_node<<<157, 128, nsm>>>(nw1, nb1, nw2, nb2, vw1, vb1, vw2, vb2);
    }
    k_copyout<<<(NN * HD + 255) / 256, 256>>>((float*)d_out);
}